// round 3
// baseline (speedup 1.0000x reference)
#include <cuda_runtime.h>

// SSIM loss: B=64, C=2, H=W=320, WIN=7 (VALID), channel-summing uniform window.
// out = 1 - mean(S), S per output pixel [64,1,314,314].

#define Hh 320
#define Ww 320
#define OH 314
#define OW 314
#define Bb 64
#define CHUNK 79
#define NCHUNK 4
#define NBLOCKS (Bb * NCHUNK)
#define NPIX (64.0 * 314.0 * 314.0)
#define GROUP 4

__device__ float g_partials[NBLOCKS];
__device__ unsigned int g_count = 0;

__global__ __launch_bounds__(320, 2) void ssim_main(
    const float* __restrict__ X, const float* __restrict__ Y,
    const float* __restrict__ data_range, const float* __restrict__ w,
    float* __restrict__ out) {
    const int t = threadIdx.x;       // input column 0..319
    const int chunk = blockIdx.x;    // 0..3
    const int b = blockIdx.y;        // 0..63
    const int y0 = chunk * CHUNK;
    const int R = min(CHUNK, OH - y0);           // output rows this block
    const int P = (R + 7) / 8;                   // 8-row super-groups

    const float w0 = w[0];                       // uniform weight (1/49)
    const float dr = data_range[b];
    const float C1 = (0.01f * dr) * (0.01f * dr);
    const float C2 = (0.03f * dr) * (0.03f * dr);
    const float cn = 49.0f / 48.0f;              // COV_NORM

    const float* __restrict__ Xb0 = X + (size_t)b * 2 * Hh * Ww;
    const float* __restrict__ Xb1 = Xb0 + Hh * Ww;
    const float* __restrict__ Yb0 = Y + (size_t)b * 2 * Hh * Ww;
    const float* __restrict__ Yb1 = Yb0 + Hh * Ww;

    __shared__ __align__(16) float sm[GROUP][5][336];
    __shared__ float red[320];
    __shared__ int s_islast;

    // zero the pad region of sm once (read by tail float4 loads)
    if (t < 16) {
#pragma unroll
        for (int r = 0; r < GROUP; ++r)
#pragma unroll
            for (int s = 0; s < 5; ++s) sm[r][s][320 + t] = 0.0f;
    }

    // 8-slot ring (rows stored at slot row&7) + running vertical sums.
    // All slot indices below are compile-time constants.
    float ring[5][8];
    float vsum[5];
#pragma unroll
    for (int s = 0; s < 5; ++s) vsum[s] = 0.0f;

    // prologue: input rows y0 .. y0+5 -> slots 0..5
#pragma unroll
    for (int r = 0; r < 6; ++r) {
        const int off = (y0 + r) * Ww + t;
        float x0 = Xb0[off], x1 = Xb1[off];
        float ya = Yb0[off], yb = Yb1[off];
        float s0 = x0 + x1;
        float s1 = ya + yb;
        float s2 = fmaf(x0, x0, x1 * x1);
        float s3 = fmaf(ya, ya, yb * yb);
        float s4 = fmaf(x0, ya, x1 * yb);
        ring[0][r] = s0; vsum[0] += s0;
        ring[1][r] = s1; vsum[1] += s1;
        ring[2][r] = s2; vsum[2] += s2;
        ring[3][r] = s3; vsum[3] += s3;
        ring[4][r] = s4; vsum[4] += s4;
    }
    ring[0][6] = ring[1][6] = ring[2][6] = ring[3][6] = ring[4][6] = 0.0f;
    ring[0][7] = ring[1][7] = ring[2][7] = ring[3][7] = ring[4][7] = 0.0f;

    // prefetch group 0's new input rows (output rows k=0..3 need input y0+6+k)
    float pf[GROUP][4];
#pragma unroll
    for (int r = 0; r < GROUP; ++r) {
        if (r < R) {
            const int off = (y0 + 6 + r) * Ww + t;
            pf[r][0] = Xb0[off]; pf[r][1] = Xb1[off];
            pf[r][2] = Yb0[off]; pf[r][3] = Yb1[off];
        } else {
            pf[r][0] = pf[r][1] = pf[r][2] = pf[r][3] = 0.0f;
        }
    }

    float acc = 0.0f;
    const int hr = t / 80;           // horizontal-phase row within group
    const int hj = t % 80;
    const int c0 = hj * 4;           // horizontal-phase base column

    for (int p = 0; p < P; ++p) {
#pragma unroll
        for (int half = 0; half < 2; ++half) {
            // ---- vertical phase: 4 rows of column sums (static ring slots) ----
#pragma unroll
            for (int r = 0; r < GROUP; ++r) {
                const int u = half * 4 + r;          // row index mod 8 (static)
                const int k = 8 * p + u;
                if (k < R) {
                    float x0 = pf[r][0], x1 = pf[r][1];
                    float ya = pf[r][2], yb = pf[r][3];
                    float s0 = x0 + x1;
                    float s1 = ya + yb;
                    float s2 = fmaf(x0, x0, x1 * x1);
                    float s3 = fmaf(ya, ya, yb * yb);
                    float s4 = fmaf(x0, ya, x1 * yb);
                    vsum[0] += s0; vsum[1] += s1; vsum[2] += s2;
                    vsum[3] += s3; vsum[4] += s4;
                    sm[r][0][t] = vsum[0];
                    sm[r][1][t] = vsum[1];
                    sm[r][2][t] = vsum[2];
                    sm[r][3][t] = vsum[3];
                    sm[r][4][t] = vsum[4];
                    const int SN = (u + 6) & 7;      // static
                    const int SO = u & 7;            // static
                    vsum[0] -= ring[0][SO]; ring[0][SN] = s0;
                    vsum[1] -= ring[1][SO]; ring[1][SN] = s1;
                    vsum[2] -= ring[2][SO]; ring[2][SN] = s2;
                    vsum[3] -= ring[3][SO]; ring[3][SN] = s3;
                    vsum[4] -= ring[4][SO]; ring[4][SN] = s4;
                }
            }

            __syncthreads();   // column sums visible

            // ---- prefetch next group's input rows (hide DRAM under horizontal) ----
#pragma unroll
            for (int r = 0; r < GROUP; ++r) {
                const int k = 8 * p + (half + 1) * 4 + r;
                if (k < R) {
                    const int off = (y0 + 6 + k) * Ww + t;
                    pf[r][0] = Xb0[off]; pf[r][1] = Xb1[off];
                    pf[r][2] = Yb0[off]; pf[r][3] = Yb1[off];
                } else {
                    pf[r][0] = pf[r][1] = pf[r][2] = pf[r][3] = 0.0f;
                }
            }

            // ---- horizontal phase: all 320 threads (4 rows x 80 col-groups) ----
            {
                const int k = 8 * p + half * 4 + hr;
                if (k < R) {
                    float h[5][4];
#pragma unroll
                    for (int s = 0; s < 5; ++s) {
                        const float4 va = *(const float4*)&sm[hr][s][c0];
                        const float4 vb = *(const float4*)&sm[hr][s][c0 + 4];
                        const float4 vc = *(const float4*)&sm[hr][s][c0 + 8];
                        float h0 = va.x + va.y + va.z + va.w + vb.x + vb.y + vb.z;
                        float h1 = h0 - va.x + vb.w;
                        float h2 = h1 - va.y + vc.x;
                        float h3 = h2 - va.z + vc.y;
                        h[s][0] = h0; h[s][1] = h1; h[s][2] = h2; h[s][3] = h3;
                    }
#pragma unroll
                    for (int i = 0; i < 4; ++i) {
                        if (c0 + i < OW) {
                            float ux  = w0 * h[0][i];
                            float uy  = w0 * h[1][i];
                            float uxx = w0 * h[2][i];
                            float uyy = w0 * h[3][i];
                            float uxy = w0 * h[4][i];
                            float vx  = cn * (uxx - ux * ux);
                            float vy  = cn * (uyy - uy * uy);
                            float vxy = cn * (uxy - ux * uy);
                            float A1 = 2.0f * ux * uy + C1;
                            float A2 = 2.0f * vxy + C2;
                            float B1 = ux * ux + uy * uy + C1;
                            float B2 = vx + vy + C2;
                            acc += __fdividef(A1 * A2, B1 * B2);
                        }
                    }
                }
            }

            __syncthreads();   // horizontal reads done before next vertical writes
        }
    }

    // ---- block reduction of acc (fixed order -> deterministic) ----
    red[t] = acc;
    __syncthreads();
    if (t < 160) red[t] += red[t + 160];
    __syncthreads();
    if (t < 80) red[t] += red[t + 80];
    __syncthreads();
    if (t < 40) red[t] += red[t + 40];
    __syncthreads();
    if (t < 20) red[t] += red[t + 20];
    __syncthreads();
    if (t < 10) red[t] += red[t + 10];
    __syncthreads();
    if (t < 5) red[t] += red[t + 5];
    __syncthreads();

    if (t == 0) {
        float v = red[0] + red[1] + red[2] + red[3] + red[4];
        g_partials[b * NCHUNK + chunk] = v;
        __threadfence();
        unsigned int old = atomicAdd(&g_count, 1u);
        s_islast = (old == NBLOCKS - 1);
    }
    __syncthreads();

    // ---- last block finishes the global reduction (deterministic order) ----
    if (s_islast) {
        __threadfence();
        red[t] = (t < NBLOCKS) ? g_partials[t] : 0.0f;
        __syncthreads();
        if (t < 160) red[t] += red[t + 160];
        __syncthreads();
        if (t < 80) red[t] += red[t + 80];
        __syncthreads();
        if (t < 40) red[t] += red[t + 40];
        __syncthreads();
        if (t < 20) red[t] += red[t + 20];
        __syncthreads();
        if (t < 10) red[t] += red[t + 10];
        __syncthreads();
        if (t < 5) red[t] += red[t + 5];
        __syncthreads();
        if (t == 0) {
            double total = (double)(red[0] + red[1] + red[2] + red[3] + red[4]);
            out[0] = (float)(1.0 - total / NPIX);
            g_count = 0;   // reset for next graph replay
        }
    }
}

extern "C" void kernel_launch(void* const* d_in, const int* in_sizes, int n_in,
                              void* d_out, int out_size) {
    const float* X  = (const float*)d_in[0];
    const float* Y  = (const float*)d_in[1];
    const float* dr = (const float*)d_in[2];
    const float* w  = (const float*)d_in[3];
    dim3 grid(NCHUNK, Bb);
    ssim_main<<<grid, 320>>>(X, Y, dr, w, (float*)d_out);
}

// round 4
// speedup vs baseline: 1.1281x; 1.1281x over previous
#include <cuda_runtime.h>

// SSIM loss: B=64, C=2, H=W=320, WIN=7 (VALID), channel-summing uniform window.
// out = 1 - mean(S), S per output pixel [64,1,314,314].

#define Hh 320
#define Ww 320
#define OH 314
#define OW 314
#define Bb 64
#define CHUNK 40
#define NCHUNK 8
#define NBLOCKS (Bb * NCHUNK)
#define NPIX (64.0 * 314.0 * 314.0)
#define GROUP 4

__device__ float g_partials[NBLOCKS];
__device__ unsigned int g_count = 0;

struct Ptrs {
    const float* Xb0; const float* Xb1;
    const float* Yb0; const float* Yb1;
};

// Main row loop. FULL=true: R == CHUNK (compile-time) -> all guards fold away.
template <bool FULL>
__device__ __forceinline__ float ssim_rows(
    const Ptrs& P_, int y0, int Rdyn, int t, int hr, int c0,
    float w0, float C1, float C2, float cn,
    float (*sm)[5][336]) {

    const int R = FULL ? CHUNK : Rdyn;
    const int P = FULL ? (CHUNK + 7) / 8 : (Rdyn + 7) / 8;

    // 8-slot ring (row stored at slot row&7) + running vertical sums.
    float ring[5][8];
    float vsum[5];
#pragma unroll
    for (int s = 0; s < 5; ++s) vsum[s] = 0.0f;

    // prologue: input rows y0 .. y0+5 -> slots 0..5
#pragma unroll
    for (int r = 0; r < 6; ++r) {
        const int off = (y0 + r) * Ww + t;
        float x0 = P_.Xb0[off], x1 = P_.Xb1[off];
        float ya = P_.Yb0[off], yb = P_.Yb1[off];
        float s0 = x0 + x1;
        float s1 = ya + yb;
        float s2 = fmaf(x0, x0, x1 * x1);
        float s3 = fmaf(ya, ya, yb * yb);
        float s4 = fmaf(x0, ya, x1 * yb);
        ring[0][r] = s0; vsum[0] += s0;
        ring[1][r] = s1; vsum[1] += s1;
        ring[2][r] = s2; vsum[2] += s2;
        ring[3][r] = s3; vsum[3] += s3;
        ring[4][r] = s4; vsum[4] += s4;
    }
#pragma unroll
    for (int s = 0; s < 5; ++s) { ring[s][6] = 0.0f; ring[s][7] = 0.0f; }

    // prefetch group 0's new input rows (output row k needs input y0+6+k)
    float pf[GROUP][4];
#pragma unroll
    for (int r = 0; r < GROUP; ++r) {
        if (r < R) {
            const int off = (y0 + 6 + r) * Ww + t;
            pf[r][0] = P_.Xb0[off]; pf[r][1] = P_.Xb1[off];
            pf[r][2] = P_.Yb0[off]; pf[r][3] = P_.Yb1[off];
        } else {
            pf[r][0] = pf[r][1] = pf[r][2] = pf[r][3] = 0.0f;
        }
    }

    float acc = 0.0f;

    for (int p = 0; p < P; ++p) {
#pragma unroll
        for (int half = 0; half < 2; ++half) {
            // ---- vertical phase: 4 rows of column sums (static ring slots) ----
#pragma unroll
            for (int r = 0; r < GROUP; ++r) {
                const int u = half * 4 + r;          // row index mod 8 (static)
                const int k = 8 * p + u;
                if (FULL || k < R) {
                    float x0 = pf[r][0], x1 = pf[r][1];
                    float ya = pf[r][2], yb = pf[r][3];
                    float s0 = x0 + x1;
                    float s1 = ya + yb;
                    float s2 = fmaf(x0, x0, x1 * x1);
                    float s3 = fmaf(ya, ya, yb * yb);
                    float s4 = fmaf(x0, ya, x1 * yb);
                    vsum[0] += s0; vsum[1] += s1; vsum[2] += s2;
                    vsum[3] += s3; vsum[4] += s4;
                    sm[r][0][t] = vsum[0];
                    sm[r][1][t] = vsum[1];
                    sm[r][2][t] = vsum[2];
                    sm[r][3][t] = vsum[3];
                    sm[r][4][t] = vsum[4];
                    const int SN = (u + 6) & 7;      // static
                    const int SO = u & 7;            // static
                    vsum[0] -= ring[0][SO]; ring[0][SN] = s0;
                    vsum[1] -= ring[1][SO]; ring[1][SN] = s1;
                    vsum[2] -= ring[2][SO]; ring[2][SN] = s2;
                    vsum[3] -= ring[3][SO]; ring[3][SN] = s3;
                    vsum[4] -= ring[4][SO]; ring[4][SN] = s4;
                }
            }

            __syncthreads();   // column sums visible

            // ---- prefetch next group (hide DRAM latency under horizontal) ----
#pragma unroll
            for (int r = 0; r < GROUP; ++r) {
                const int k = 8 * p + (half + 1) * 4 + r;
                if (k < R) {
                    const int off = (y0 + 6 + k) * Ww + t;
                    pf[r][0] = P_.Xb0[off]; pf[r][1] = P_.Xb1[off];
                    pf[r][2] = P_.Yb0[off]; pf[r][3] = P_.Yb1[off];
                } else {
                    pf[r][0] = pf[r][1] = pf[r][2] = pf[r][3] = 0.0f;
                }
            }

            // ---- horizontal phase: all 320 threads (4 rows x 80 col-groups) ----
            {
                const int k = 8 * p + half * 4 + hr;
                if (FULL || k < R) {
                    float h[5][4];
#pragma unroll
                    for (int s = 0; s < 5; ++s) {
                        const float4 va = *(const float4*)&sm[hr][s][c0];
                        const float4 vb = *(const float4*)&sm[hr][s][c0 + 4];
                        const float4 vc = *(const float4*)&sm[hr][s][c0 + 8];
                        float h0 = va.x + va.y + va.z + va.w + vb.x + vb.y + vb.z;
                        float h1 = h0 - va.x + vb.w;
                        float h2 = h1 - va.y + vc.x;
                        float h3 = h2 - va.z + vc.y;
                        h[s][0] = h0; h[s][1] = h1; h[s][2] = h2; h[s][3] = h3;
                    }
#pragma unroll
                    for (int i = 0; i < 4; ++i) {
                        if (c0 + i < OW) {
                            float ux  = w0 * h[0][i];
                            float uy  = w0 * h[1][i];
                            float uxx = w0 * h[2][i];
                            float uyy = w0 * h[3][i];
                            float uxy = w0 * h[4][i];
                            float vx  = cn * (uxx - ux * ux);
                            float vy  = cn * (uyy - uy * uy);
                            float vxy = cn * (uxy - ux * uy);
                            float A1 = 2.0f * ux * uy + C1;
                            float A2 = 2.0f * vxy + C2;
                            float B1 = ux * ux + uy * uy + C1;
                            float B2 = vx + vy + C2;
                            acc += __fdividef(A1 * A2, B1 * B2);
                        }
                    }
                }
            }

            __syncthreads();   // horizontal reads done before next vertical writes
        }
    }
    return acc;
}

__global__ __launch_bounds__(320, 2) void ssim_main(
    const float* __restrict__ X, const float* __restrict__ Y,
    const float* __restrict__ data_range, const float* __restrict__ w,
    float* __restrict__ out) {
    const int t = threadIdx.x;       // input column 0..319
    const int chunk = blockIdx.x;    // 0..7
    const int b = blockIdx.y;        // 0..63
    const int y0 = chunk * CHUNK;
    const int R = min(CHUNK, OH - y0);           // 40, except last chunk: 34

    const float w0 = w[0];                       // uniform weight (1/49)
    const float dr = data_range[b];
    const float C1 = (0.01f * dr) * (0.01f * dr);
    const float C2 = (0.03f * dr) * (0.03f * dr);
    const float cn = 49.0f / 48.0f;              // COV_NORM

    Ptrs P_;
    P_.Xb0 = X + (size_t)b * 2 * Hh * Ww;
    P_.Xb1 = P_.Xb0 + Hh * Ww;
    P_.Yb0 = Y + (size_t)b * 2 * Hh * Ww;
    P_.Yb1 = P_.Yb0 + Hh * Ww;

    __shared__ __align__(16) float sm[GROUP][5][336];
    __shared__ float red[320];
    __shared__ int s_islast;

    // zero the pad region of sm once (read by tail float4 loads)
    if (t < 16) {
#pragma unroll
        for (int r = 0; r < GROUP; ++r)
#pragma unroll
            for (int s = 0; s < 5; ++s) sm[r][s][320 + t] = 0.0f;
    }
    __syncthreads();

    const int hr = t / 80;           // horizontal-phase row within group
    const int hj = t % 80;
    const int c0 = hj * 4;           // horizontal-phase base column

    float acc;
    if (R == CHUNK)
        acc = ssim_rows<true>(P_, y0, R, t, hr, c0, w0, C1, C2, cn, sm);
    else
        acc = ssim_rows<false>(P_, y0, R, t, hr, c0, w0, C1, C2, cn, sm);

    // ---- block reduction of acc (fixed order -> deterministic) ----
    red[t] = acc;
    __syncthreads();
    if (t < 160) red[t] += red[t + 160];
    __syncthreads();
    if (t < 80) red[t] += red[t + 80];
    __syncthreads();
    if (t < 40) red[t] += red[t + 40];
    __syncthreads();
    if (t < 20) red[t] += red[t + 20];
    __syncthreads();
    if (t < 10) red[t] += red[t + 10];
    __syncthreads();
    if (t < 5) red[t] += red[t + 5];
    __syncthreads();

    if (t == 0) {
        float v = red[0] + red[1] + red[2] + red[3] + red[4];
        g_partials[b * NCHUNK + chunk] = v;
        __threadfence();
        unsigned int old = atomicAdd(&g_count, 1u);
        s_islast = (old == NBLOCKS - 1);
    }
    __syncthreads();

    // ---- last block finishes the global reduction (deterministic order) ----
    if (s_islast) {
        __threadfence();
        float v = g_partials[t];
        if (t < NBLOCKS - 320) v += g_partials[t + 320];
        red[t] = v;
        __syncthreads();
        if (t < 160) red[t] += red[t + 160];
        __syncthreads();
        if (t < 80) red[t] += red[t + 80];
        __syncthreads();
        if (t < 40) red[t] += red[t + 40];
        __syncthreads();
        if (t < 20) red[t] += red[t + 20];
        __syncthreads();
        if (t < 10) red[t] += red[t + 10];
        __syncthreads();
        if (t < 5) red[t] += red[t + 5];
        __syncthreads();
        if (t == 0) {
            double total = (double)(red[0] + red[1] + red[2] + red[3] + red[4]);
            out[0] = (float)(1.0 - total / NPIX);
            g_count = 0;   // reset for next graph replay
        }
    }
}

extern "C" void kernel_launch(void* const* d_in, const int* in_sizes, int n_in,
                              void* d_out, int out_size) {
    const float* X  = (const float*)d_in[0];
    const float* Y  = (const float*)d_in[1];
    const float* dr = (const float*)d_in[2];
    const float* w  = (const float*)d_in[3];
    dim3 grid(NCHUNK, Bb);
    ssim_main<<<grid, 320>>>(X, Y, dr, w, (float*)d_out);
}

// round 5
// speedup vs baseline: 1.1773x; 1.0436x over previous
#include <cuda_runtime.h>

// SSIM loss: B=64, C=2, H=W=320, WIN=7 (VALID), channel-summing uniform window.
// out = 1 - mean(S), S per output pixel [64,1,314,314].

#define Hh 320
#define Ww 320
#define OH 314
#define OW 314
#define Bb 64
#define CHUNK 40
#define NCHUNK 8
#define NBLOCKS (Bb * NCHUNK)
#define NPIX (64.0 * 314.0 * 314.0)
#define GROUP 4
#define ROWLEN 328                       // floats per (row,stat) lane; mult of 4
#define BUFSZ (GROUP * 5 * ROWLEN)       // one group buffer, floats
#define SMEM_BYTES (2 * BUFSZ * 4)       // two buffers

__device__ float g_partials[NBLOCKS];
__device__ unsigned int g_count = 0;

struct Ptrs {
    const float* Xb0; const float* Xb1;
    const float* Yb0; const float* Yb1;
};

#define SM(buf, r, s, i) (buf)[(((r) * 5 + (s)) * ROWLEN) + (i)]

// Main row loop. FULL=true: R == CHUNK (compile-time) -> guards fold away.
template <bool FULL>
__device__ __forceinline__ float ssim_rows(
    const Ptrs& P_, int y0, int Rdyn, int t, int hr, int c0,
    float w0, float C1, float C2, float cn,
    float* __restrict__ sm0, float* __restrict__ sm1) {

    const int R = FULL ? CHUNK : Rdyn;
    const int P = FULL ? (CHUNK + 7) / 8 : (Rdyn + 7) / 8;

    // 8-slot ring (row stored at slot row&7) + running vertical sums.
    float ring[5][8];
    float vsum[5];
#pragma unroll
    for (int s = 0; s < 5; ++s) vsum[s] = 0.0f;

    // prologue: input rows y0 .. y0+5 -> slots 0..5
#pragma unroll
    for (int r = 0; r < 6; ++r) {
        const int off = (y0 + r) * Ww + t;
        float x0 = P_.Xb0[off], x1 = P_.Xb1[off];
        float ya = P_.Yb0[off], yb = P_.Yb1[off];
        float s0 = x0 + x1;
        float s1 = ya + yb;
        float s2 = fmaf(x0, x0, x1 * x1);
        float s3 = fmaf(ya, ya, yb * yb);
        float s4 = fmaf(x0, ya, x1 * yb);
        ring[0][r] = s0; vsum[0] += s0;
        ring[1][r] = s1; vsum[1] += s1;
        ring[2][r] = s2; vsum[2] += s2;
        ring[3][r] = s3; vsum[3] += s3;
        ring[4][r] = s4; vsum[4] += s4;
    }
#pragma unroll
    for (int s = 0; s < 5; ++s) { ring[s][6] = 0.0f; ring[s][7] = 0.0f; }

    // prefetch group 0's new input rows (output row k needs input y0+6+k)
    float pf[GROUP][4];
#pragma unroll
    for (int r = 0; r < GROUP; ++r) {
        if (r < R) {
            const int off = (y0 + 6 + r) * Ww + t;
            pf[r][0] = P_.Xb0[off]; pf[r][1] = P_.Xb1[off];
            pf[r][2] = P_.Yb0[off]; pf[r][3] = P_.Yb1[off];
        } else {
            pf[r][0] = pf[r][1] = pf[r][2] = pf[r][3] = 0.0f;
        }
    }

    float acc = 0.0f;

#pragma unroll 1
    for (int p = 0; p < P; ++p) {
#pragma unroll
        for (int half = 0; half < 2; ++half) {
            float* __restrict__ buf = half ? sm1 : sm0;   // group parity == half

            // ---- vertical phase: 4 rows of column sums (static ring slots) ----
#pragma unroll
            for (int r = 0; r < GROUP; ++r) {
                const int u = half * 4 + r;          // row index mod 8 (static)
                const int k = 8 * p + u;
                if (FULL || k < R) {
                    float x0 = pf[r][0], x1 = pf[r][1];
                    float ya = pf[r][2], yb = pf[r][3];
                    float s0 = x0 + x1;
                    float s1 = ya + yb;
                    float s2 = fmaf(x0, x0, x1 * x1);
                    float s3 = fmaf(ya, ya, yb * yb);
                    float s4 = fmaf(x0, ya, x1 * yb);
                    vsum[0] += s0; vsum[1] += s1; vsum[2] += s2;
                    vsum[3] += s3; vsum[4] += s4;
                    SM(buf, r, 0, t) = vsum[0];
                    SM(buf, r, 1, t) = vsum[1];
                    SM(buf, r, 2, t) = vsum[2];
                    SM(buf, r, 3, t) = vsum[3];
                    SM(buf, r, 4, t) = vsum[4];
                    const int SN = (u + 6) & 7;      // static
                    const int SO = u & 7;            // static
                    vsum[0] -= ring[0][SO]; ring[0][SN] = s0;
                    vsum[1] -= ring[1][SO]; ring[1][SN] = s1;
                    vsum[2] -= ring[2][SO]; ring[2][SN] = s2;
                    vsum[3] -= ring[3][SO]; ring[3][SN] = s3;
                    vsum[4] -= ring[4][SO]; ring[4][SN] = s4;
                }
            }

            // ---- prefetch next group BEFORE barrier (loads fly during wait) ----
#pragma unroll
            for (int r = 0; r < GROUP; ++r) {
                const int k = 8 * p + (half + 1) * 4 + r;
                if (k < R) {
                    const int off = (y0 + 6 + k) * Ww + t;
                    pf[r][0] = P_.Xb0[off]; pf[r][1] = P_.Xb1[off];
                    pf[r][2] = P_.Yb0[off]; pf[r][3] = P_.Yb1[off];
                } else {
                    pf[r][0] = pf[r][1] = pf[r][2] = pf[r][3] = 0.0f;
                }
            }

            __syncthreads();   // single barrier: column sums visible

            // ---- horizontal phase: all 320 threads (4 rows x 80 col-groups) ----
            // No trailing barrier: next group writes the OTHER buffer; this
            // buffer is rewritten only after the NEXT sync, by which time all
            // threads have finished these reads (program order).
            {
                const int k = 8 * p + half * 4 + hr;
                if (FULL || k < R) {
                    float h[5][4];
#pragma unroll
                    for (int s = 0; s < 5; ++s) {
                        const float4 va = *(const float4*)&SM(buf, hr, s, c0);
                        const float4 vb = *(const float4*)&SM(buf, hr, s, c0 + 4);
                        const float4 vc = *(const float4*)&SM(buf, hr, s, c0 + 8);
                        float h0 = va.x + va.y + va.z + va.w + vb.x + vb.y + vb.z;
                        float h1 = h0 - va.x + vb.w;
                        float h2 = h1 - va.y + vc.x;
                        float h3 = h2 - va.z + vc.y;
                        h[s][0] = h0; h[s][1] = h1; h[s][2] = h2; h[s][3] = h3;
                    }
#pragma unroll
                    for (int i = 0; i < 4; ++i) {
                        if (c0 + i < OW) {
                            float ux  = w0 * h[0][i];
                            float uy  = w0 * h[1][i];
                            float uxx = w0 * h[2][i];
                            float uyy = w0 * h[3][i];
                            float uxy = w0 * h[4][i];
                            float vx  = cn * (uxx - ux * ux);
                            float vy  = cn * (uyy - uy * uy);
                            float vxy = cn * (uxy - ux * uy);
                            float A1 = 2.0f * ux * uy + C1;
                            float A2 = 2.0f * vxy + C2;
                            float B1 = ux * ux + uy * uy + C1;
                            float B2 = vx + vy + C2;
                            acc += __fdividef(A1 * A2, B1 * B2);
                        }
                    }
                }
            }
        }
    }
    return acc;
}

__global__ __launch_bounds__(320, 2) void ssim_main(
    const float* __restrict__ X, const float* __restrict__ Y,
    const float* __restrict__ data_range, const float* __restrict__ w,
    float* __restrict__ out) {
    extern __shared__ float dsm[];
    float* sm0 = dsm;
    float* sm1 = dsm + BUFSZ;

    const int t = threadIdx.x;       // input column 0..319
    const int chunk = blockIdx.x;    // 0..7
    const int b = blockIdx.y;        // 0..63
    const int y0 = chunk * CHUNK;
    const int R = min(CHUNK, OH - y0);           // 40, except last chunk: 34

    const float w0 = w[0];                       // uniform weight (1/49)
    const float dr = data_range[b];
    const float C1 = (0.01f * dr) * (0.01f * dr);
    const float C2 = (0.03f * dr) * (0.03f * dr);
    const float cn = 49.0f / 48.0f;              // COV_NORM

    Ptrs P_;
    P_.Xb0 = X + (size_t)b * 2 * Hh * Ww;
    P_.Xb1 = P_.Xb0 + Hh * Ww;
    P_.Yb0 = Y + (size_t)b * 2 * Hh * Ww;
    P_.Yb1 = P_.Yb0 + Hh * Ww;

    __shared__ float red[320];
    __shared__ int s_islast;

    const int hr = t / 80;           // horizontal-phase row within group
    const int hj = t % 80;
    const int c0 = hj * 4;           // horizontal-phase base column

    float acc;
    if (R == CHUNK)
        acc = ssim_rows<true>(P_, y0, R, t, hr, c0, w0, C1, C2, cn, sm0, sm1);
    else
        acc = ssim_rows<false>(P_, y0, R, t, hr, c0, w0, C1, C2, cn, sm0, sm1);

    // ---- block reduction of acc (fixed order -> deterministic) ----
    __syncthreads();
    red[t] = acc;
    __syncthreads();
    if (t < 160) red[t] += red[t + 160];
    __syncthreads();
    if (t < 80) red[t] += red[t + 80];
    __syncthreads();
    if (t < 40) red[t] += red[t + 40];
    __syncthreads();
    if (t < 20) red[t] += red[t + 20];
    __syncthreads();
    if (t < 10) red[t] += red[t + 10];
    __syncthreads();
    if (t < 5) red[t] += red[t + 5];
    __syncthreads();

    if (t == 0) {
        float v = red[0] + red[1] + red[2] + red[3] + red[4];
        g_partials[b * NCHUNK + chunk] = v;
        __threadfence();
        unsigned int old = atomicAdd(&g_count, 1u);
        s_islast = (old == NBLOCKS - 1);
    }
    __syncthreads();

    // ---- last block finishes the global reduction (deterministic order) ----
    if (s_islast) {
        __threadfence();
        float v = g_partials[t];
        if (t < NBLOCKS - 320) v += g_partials[t + 320];
        red[t] = v;
        __syncthreads();
        if (t < 160) red[t] += red[t + 160];
        __syncthreads();
        if (t < 80) red[t] += red[t + 80];
        __syncthreads();
        if (t < 40) red[t] += red[t + 40];
        __syncthreads();
        if (t < 20) red[t] += red[t + 20];
        __syncthreads();
        if (t < 10) red[t] += red[t + 10];
        __syncthreads();
        if (t < 5) red[t] += red[t + 5];
        __syncthreads();
        if (t == 0) {
            double total = (double)(red[0] + red[1] + red[2] + red[3] + red[4]);
            out[0] = (float)(1.0 - total / NPIX);
            g_count = 0;   // reset for next graph replay
        }
    }
}

extern "C" void kernel_launch(void* const* d_in, const int* in_sizes, int n_in,
                              void* d_out, int out_size) {
    const float* X  = (const float*)d_in[0];
    const float* Y  = (const float*)d_in[1];
    const float* dr = (const float*)d_in[2];
    const float* w  = (const float*)d_in[3];
    cudaFuncSetAttribute(ssim_main, cudaFuncAttributeMaxDynamicSharedMemorySize,
                         SMEM_BYTES);
    dim3 grid(NCHUNK, Bb);
    ssim_main<<<grid, 320, SMEM_BYTES>>>(X, Y, dr, w, (float*)d_out);
}